// round 2
// baseline (speedup 1.0000x reference)
#include <cuda_runtime.h>
#include <math.h>

#define Bn   4
#define HWp  16384
#define LSEQ 16384

// ---------------- scratch ----------------
__device__ float g_xT[Bn*HWp*64];        // [b][pix][c]
__device__ float g_rawoff[Bn*HWp*10];    // offset conv out ch0..9
__device__ float g_ostats[Bn*5*2];
__device__ float g_seq[Bn*9*LSEQ];       // [b][m][l]
__device__ float g_ynew[Bn*9*HWp];       // [b][k][pix]
__device__ float g_dt[Bn*18*LSEQ];
__device__ float g_xi[Bn*18*LSEQ];
__device__ float g_gate[Bn*18*LSEQ];     // silu(z)
__device__ float g_Bsc[Bn*16*LSEQ];
__device__ float g_Csc[Bn*16*LSEQ];
__device__ float g_P[Bn*64*288];
__device__ float g_Q[Bn*64*288];
__device__ float g_hinit[Bn*64*288];
__device__ float g_py[Bn*9*HWp];         // [b][k][pix]
__device__ float g_wT[9*64*64];          // [k][ci][co]
__device__ float g_outraw[Bn*64*HWp];
__device__ float g_fstats[Bn*16*2];

__device__ __forceinline__ float softplusf(float x){
    return x > 20.f ? x : log1pf(expf(x));
}
__device__ __forceinline__ float siluf(float x){
    return x / (1.f + expf(-x));
}

// ---------------- zero stats ----------------
__global__ void kZero(){
    int t = threadIdx.x;
    if (t < 40)  g_ostats[t] = 0.f;
    if (t < 128) g_fstats[t] = 0.f;
}

// ---------------- transpose x ----------------
__global__ void kTranspose(const float* __restrict__ x){
    __shared__ float tile[32][33];
    int b = blockIdx.z, c0 = blockIdx.y*32, p0 = blockIdx.x*32;
    for (int i = threadIdx.y; i < 32; i += 8)
        tile[i][threadIdx.x] = x[(size_t)(b*64 + c0 + i)*HWp + p0 + threadIdx.x];
    __syncthreads();
    for (int i = threadIdx.y; i < 32; i += 8)
        g_xT[(size_t)(b*HWp + p0 + i)*64 + c0 + threadIdx.x] = tile[threadIdx.x][i];
}

// ---------------- weight transpose for deform conv ----------------
__global__ void kPrepW(const float* __restrict__ dscw){
    int idx = blockIdx.x*256 + threadIdx.x;
    if (idx >= 9*64*64) return;
    int k = idx >> 12; int r = idx & 4095;
    int ci = r >> 6;  int co = r & 63;
    g_wT[idx] = dscw[(co*64 + ci)*9 + k];
}

// ---------------- offset conv 3x3 64->10 + GN stats ----------------
#define CONV_SMEM ((3*130*65 + 5760)*4)
__global__ void kConv(const float* __restrict__ offw, const float* __restrict__ offb){
    extern __shared__ float sm[];
    float* xs = sm;               // [j 0..2][wp 0..129][c 0..63] stride 65
    float* ws = sm + 3*130*65;    // [(c*3+dy)*3+dx]*10 + co
    int h = blockIdx.x, b = blockIdx.y, tid = threadIdx.x;

    for (int idx = tid; idx < 5760; idx += 128){
        int co = idx % 10; int r = idx / 10;
        int dx = r % 3; int r2 = r / 3;
        int dy = r2 % 3; int c = r2 / 3;
        ws[idx] = offw[((co*64 + c)*3 + dy)*3 + dx];
    }
    for (int idx = tid; idx < 3*130*64; idx += 128){
        int c = idx & 63; int r = idx >> 6;
        int wp = r % 130; int j = r / 130;
        int yy = h - 1 + j, wx = wp - 1;
        float v = 0.f;
        if (yy >= 0 && yy < 128 && wx >= 0 && wx < 128)
            v = g_xT[((size_t)b*HWp + yy*128 + wx)*64 + c];
        xs[(j*130 + wp)*65 + c] = v;
    }
    __syncthreads();

    int w = tid;
    float acc[10];
    #pragma unroll
    for (int co = 0; co < 10; co++) acc[co] = offb[co];

    for (int dy = 0; dy < 3; dy++){
        for (int c = 0; c < 64; c++){
            float x0 = xs[(dy*130 + w    )*65 + c];
            float x1 = xs[(dy*130 + w + 1)*65 + c];
            float x2 = xs[(dy*130 + w + 2)*65 + c];
            const float* wb = &ws[(c*3 + dy)*30];
            #pragma unroll
            for (int co = 0; co < 10; co++)
                acc[co] += wb[co]*x0 + wb[10+co]*x1 + wb[20+co]*x2;
        }
    }
    float* rp = &g_rawoff[((size_t)b*HWp + h*128 + w)*10];
    #pragma unroll
    for (int co = 0; co < 10; co++) rp[co] = acc[co];

    #pragma unroll
    for (int g = 0; g < 5; g++){
        float s  = acc[2*g] + acc[2*g+1];
        float ss = acc[2*g]*acc[2*g] + acc[2*g+1]*acc[2*g+1];
        #pragma unroll
        for (int m = 16; m > 0; m >>= 1){
            s  += __shfl_xor_sync(0xffffffffu, s,  m);
            ss += __shfl_xor_sync(0xffffffffu, ss, m);
        }
        if ((tid & 31) == 0){
            atomicAdd(&g_ostats[(b*5+g)*2    ], s);
            atomicAdd(&g_ostats[(b*5+g)*2 + 1], ss);
        }
    }
}

// ---------------- GN finalize + tanh + cumsum + seq + y_new ----------------
__global__ void kFinishOff(const float* __restrict__ gnog, const float* __restrict__ gnob){
    __shared__ float sMu[5], sRs[5];
    int b = blockIdx.y, tid = threadIdx.x;
    int p = blockIdx.x*256 + tid;
    if (tid < 5){
        float s  = g_ostats[(b*5+tid)*2];
        float ss = g_ostats[(b*5+tid)*2+1];
        float mu = s * (1.f/32768.f);
        float var = ss * (1.f/32768.f) - mu*mu;
        sMu[tid] = mu;
        sRs[tid] = rsqrtf(var + 1e-5f);
    }
    __syncthreads();

    float raw[9], tv[9];
    const float* rp = &g_rawoff[((size_t)b*HWp + p)*10];
    #pragma unroll
    for (int c = 0; c < 9; c++) raw[c] = rp[c];
    #pragma unroll
    for (int c = 0; c < 9; c++){
        float xn = (raw[c] - sMu[c>>1]) * sRs[c>>1] * gnog[c] + gnob[c];
        tv[c] = tanhf(xn);
    }
    float cum[9];
    cum[4] = 0.f;
    cum[5] = tv[5]; cum[6] = cum[5]+tv[6]; cum[7] = cum[6]+tv[7]; cum[8] = cum[7]+tv[8];
    cum[3] = tv[3]; cum[2] = cum[3]+tv[2]; cum[1] = cum[2]+tv[1]; cum[0] = cum[1]+tv[0];

    int h = p >> 7, w = p & 127;
    #pragma unroll
    for (int k = 0; k < 9; k++)
        g_ynew[((size_t)(b*9+k))*HWp + p] = (float)h + cum[k];

    int l = ((h>>1)*128 + w)*2 + (h&1);
    #pragma unroll
    for (int m = 0; m < 9; m++)
        g_seq[((size_t)(b*9+m))*LSEQ + l] = tv[m];
}

// ---------------- mamba front-end ----------------
__global__ void kFrontEnd(const float* __restrict__ ipw, const float* __restrict__ cw,
                          const float* __restrict__ cb,  const float* __restrict__ xpw,
                          const float* __restrict__ dtw, const float* __restrict__ dtb){
    __shared__ float sXP[259*19];
    __shared__ float sIPW[324], sXPW[594], sCW[72], sCB[18], sDTW[18], sDTB[18];
    int b = blockIdx.y, l0 = blockIdx.x*256, tid = threadIdx.x;
    int l = l0 + tid;

    for (int idx = tid; idx < 324; idx += 256) sIPW[idx] = ipw[idx];
    for (int idx = tid; idx < 594; idx += 256) sXPW[idx] = xpw[idx];
    if (tid < 72) sCW[tid] = cw[tid];
    if (tid < 18){ sCB[tid] = cb[tid]; sDTW[tid] = dtw[tid]; sDTB[tid] = dtb[tid]; }
    __syncthreads();

    float sq[9];
    #pragma unroll
    for (int m = 0; m < 9; m++) sq[m] = g_seq[((size_t)(b*9+m))*LSEQ + l];
    #pragma unroll
    for (int n = 0; n < 18; n++){
        float v = 0.f;
        #pragma unroll
        for (int m = 0; m < 9; m++) v += sq[m]*sIPW[n*9+m];
        sXP[(tid+3)*19 + n] = v;
    }
    #pragma unroll
    for (int n = 0; n < 18; n++){
        float z = 0.f;
        #pragma unroll
        for (int m = 0; m < 9; m++) z += sq[m]*sIPW[(18+n)*9+m];
        g_gate[((size_t)(b*18+n))*LSEQ + l] = siluf(z);
    }
    if (tid < 3){
        int l2 = l0 - 3 + tid;
        if (l2 >= 0){
            float s2[9];
            #pragma unroll
            for (int m = 0; m < 9; m++) s2[m] = g_seq[((size_t)(b*9+m))*LSEQ + l2];
            #pragma unroll
            for (int n = 0; n < 18; n++){
                float v = 0.f;
                #pragma unroll
                for (int m = 0; m < 9; m++) v += s2[m]*sIPW[n*9+m];
                sXP[tid*19 + n] = v;
            }
        } else {
            #pragma unroll
            for (int n = 0; n < 18; n++) sXP[tid*19 + n] = 0.f;
        }
    }
    __syncthreads();

    float xi[18];
    #pragma unroll
    for (int d = 0; d < 18; d++){
        float xc = sCB[d];
        #pragma unroll
        for (int j = 0; j < 4; j++) xc += sCW[d*4+j]*sXP[(tid+j)*19 + d];
        xi[d] = siluf(xc);
    }
    float dtr = 0.f;
    #pragma unroll
    for (int d = 0; d < 18; d++) dtr += xi[d]*sXPW[d];
    #pragma unroll
    for (int s = 0; s < 16; s++){
        float bv = 0.f, cv = 0.f;
        #pragma unroll
        for (int d = 0; d < 18; d++){
            bv += xi[d]*sXPW[(1+s)*18 + d];
            cv += xi[d]*sXPW[(17+s)*18 + d];
        }
        g_Bsc[((size_t)(b*16+s))*LSEQ + l] = bv;
        g_Csc[((size_t)(b*16+s))*LSEQ + l] = cv;
    }
    #pragma unroll
    for (int d = 0; d < 18; d++){
        float a = dtr*sDTW[d] + sDTB[d];
        g_dt[((size_t)(b*18+d))*LSEQ + l] = softplusf(a);
        g_xi[((size_t)(b*18+d))*LSEQ + l] = xi[d];
    }
}

// ---------------- scan pass1: per-chunk (P,Q) ----------------
#define SCAN1_SMEM (52*257*4)
__global__ void kScan1(const float* __restrict__ Alog){
    extern __shared__ float sm[];
    float* sDT = sm;
    float* sXI = sm + 18*257;
    float* sB  = sm + 36*257;
    int b = blockIdx.y, c = blockIdx.x, l0 = c*256, t = threadIdx.x;
    for (int idx = t; idx < 18*256; idx += 288){
        int dd = idx >> 8, i = idx & 255;
        sDT[dd*257+i] = g_dt[((size_t)(b*18+dd))*LSEQ + l0 + i];
        sXI[dd*257+i] = g_xi[((size_t)(b*18+dd))*LSEQ + l0 + i];
    }
    for (int idx = t; idx < 16*256; idx += 288){
        int ss = idx >> 8, i = idx & 255;
        sB[ss*257+i] = g_Bsc[((size_t)(b*16+ss))*LSEQ + l0 + i];
    }
    __syncthreads();
    int d = t / 16, s = t % 16;
    float a = -expf(Alog[d*16+s]);
    float p = 1.f, q = 0.f;
    for (int i = 0; i < 256; i++){
        float dt = sDT[d*257+i];
        float da = expf(dt*a);
        q = da*q + dt*sB[s*257+i]*sXI[d*257+i];
        p *= da;
    }
    g_P[(b*64+c)*288 + t] = p;
    g_Q[(b*64+c)*288 + t] = q;
}

// ---------------- scan pass2: serial carry ----------------
__global__ void kScan2(){
    int b = blockIdx.x, t = threadIdx.x;
    float h = 0.f;
    for (int c = 0; c < 64; c++){
        g_hinit[(b*64+c)*288 + t] = h;
        h = g_P[(b*64+c)*288 + t]*h + g_Q[(b*64+c)*288 + t];
    }
}

// ---------------- scan pass3: replay + output + py ----------------
#define SCAN3_SMEM ((86*257 + 162 + 18)*4)
__global__ void kScan3(const float* __restrict__ Alog, const float* __restrict__ Dp,
                       const float* __restrict__ opw,  const float* __restrict__ altho){
    extern __shared__ float sm[];
    float* sDT = sm;
    float* sXI = sm + 18*257;
    float* sB  = sm + 36*257;
    float* sC  = sm + 52*257;
    float* sYS = sm + 68*257;
    float* sOPW = sm + 86*257;
    float* sDP  = sOPW + 162;
    int b = blockIdx.y, c = blockIdx.x, l0 = c*256, t = threadIdx.x;
    for (int idx = t; idx < 18*256; idx += 288){
        int dd = idx >> 8, i = idx & 255;
        sDT[dd*257+i] = g_dt[((size_t)(b*18+dd))*LSEQ + l0 + i];
        sXI[dd*257+i] = g_xi[((size_t)(b*18+dd))*LSEQ + l0 + i];
    }
    for (int idx = t; idx < 16*256; idx += 288){
        int ss = idx >> 8, i = idx & 255;
        sB[ss*257+i] = g_Bsc[((size_t)(b*16+ss))*LSEQ + l0 + i];
        sC[ss*257+i] = g_Csc[((size_t)(b*16+ss))*LSEQ + l0 + i];
    }
    if (t < 162) sOPW[t] = opw[t];
    if (t < 18)  sDP[t]  = Dp[t];
    __syncthreads();

    int d = t / 16, s = t % 16;
    float a = -expf(Alog[d*16+s]);
    float h = g_hinit[(b*64+c)*288 + t];
    for (int i = 0; i < 256; i++){
        float dt = sDT[d*257+i];
        float da = expf(dt*a);
        h = da*h + dt*sB[s*257+i]*sXI[d*257+i];
        float v = h * sC[s*257+i];
        v += __shfl_xor_sync(0xffffffffu, v, 1);
        v += __shfl_xor_sync(0xffffffffu, v, 2);
        v += __shfl_xor_sync(0xffffffffu, v, 4);
        v += __shfl_xor_sync(0xffffffffu, v, 8);
        if ((t & 15) == 0) sYS[d*257+i] = v;
    }
    __syncthreads();

    if (t < 256){
        int l = l0 + t;
        float wgt = fmaxf(softplusf(altho[0]), 0.01f);
        float ym[9];
        #pragma unroll
        for (int m = 0; m < 9; m++) ym[m] = 0.f;
        #pragma unroll
        for (int dd = 0; dd < 18; dd++){
            float yv = (sYS[dd*257+t] + sDP[dd]*sXI[dd*257+t]) * g_gate[((size_t)(b*18+dd))*LSEQ + l];
            #pragma unroll
            for (int m = 0; m < 9; m++) ym[m] += yv * sOPW[m*18+dd];
        }
        int tt = l & 1, r = l >> 1;
        int w = r & 127, h2 = r >> 7;
        int pix = (h2*2 + tt)*128 + w;
        #pragma unroll
        for (int m = 0; m < 9; m++){
            float py = wgt*ym[m] + g_ynew[((size_t)(b*9+m))*HWp + pix];
            py = fminf(fmaxf(py, 0.f), 127.f);
            g_py[((size_t)(b*9+m))*HWp + pix] = py;
        }
    }
}

// ---------------- deformable gather + 64x576 contraction + GN stats ----------------
#define DEF_SMEM (12288*4)
__global__ void __launch_bounds__(256) kDeform(const float* __restrict__ dscb){
    extern __shared__ float sm[];
    float* sVal = sm;          // [ci][j] 64x128
    float* sW   = sm + 8192;   // [ci][co] 64x64
    int i = blockIdx.x, b = blockIdx.y, t = threadIdx.x;
    int coq = t >> 5, lq = t & 31;
    int j = t >> 1, half = t & 1;

    float acc[4][8];
    #pragma unroll
    for (int a = 0; a < 4; a++)
        #pragma unroll
        for (int c2 = 0; c2 < 8; c2++) acc[a][c2] = 0.f;

    for (int k = 0; k < 9; k++){
        #pragma unroll
        for (int r = 0; r < 16; r++) sW[t + 256*r] = g_wT[k*4096 + t + 256*r];

        float pyv = g_py[((size_t)(b*9+k))*HWp + i*128 + j];
        int y0 = (int)floorf(pyv);
        float wy = pyv - (float)y0;
        int y1 = min(y0 + 1, 127);
        int xc = min(max(j + k - 4, 0), 127);
        const float* r0 = &g_xT[((size_t)b*HWp + y0*128 + xc)*64 + half*32];
        const float* r1 = &g_xT[((size_t)b*HWp + y1*128 + xc)*64 + half*32];
        float wy0 = 1.f - wy;
        #pragma unroll
        for (int c2 = 0; c2 < 32; c2++)
            sVal[(half*32 + c2)*128 + j] = r0[c2]*wy0 + r1[c2]*wy;
        __syncthreads();

        #pragma unroll 2
        for (int ci = 0; ci < 64; ci++){
            float v0 = sVal[ci*128 + lq];
            float v1 = sVal[ci*128 + lq + 32];
            float v2 = sVal[ci*128 + lq + 64];
            float v3 = sVal[ci*128 + lq + 96];
            float4 wA = *(const float4*)&sW[ci*64 + coq*8];
            float4 wB = *(const float4*)&sW[ci*64 + coq*8 + 4];
            float wv[8] = {wA.x, wA.y, wA.z, wA.w, wB.x, wB.y, wB.z, wB.w};
            float vv[4] = {v0, v1, v2, v3};
            #pragma unroll
            for (int jj = 0; jj < 4; jj++)
                #pragma unroll
                for (int c2 = 0; c2 < 8; c2++)
                    acc[jj][c2] += wv[c2]*vv[jj];
        }
        __syncthreads();
    }

    float gs[2] = {0.f, 0.f}, gss[2] = {0.f, 0.f};
    #pragma unroll
    for (int c2 = 0; c2 < 8; c2++){
        int co = coq*8 + c2;
        float bsv = dscb[co];
        #pragma unroll
        for (int jj = 0; jj < 4; jj++){
            float v = acc[jj][c2] + bsv;
            g_outraw[((size_t)(b*64+co))*HWp + i*128 + lq + 32*jj] = v;
            gs[c2>>2] += v; gss[c2>>2] += v*v;
        }
    }
    #pragma unroll
    for (int gg = 0; gg < 2; gg++){
        float s = gs[gg], ss = gss[gg];
        #pragma unroll
        for (int m = 16; m > 0; m >>= 1){
            s  += __shfl_xor_sync(0xffffffffu, s,  m);
            ss += __shfl_xor_sync(0xffffffffu, ss, m);
        }
        if (lq == 0){
            atomicAdd(&g_fstats[(b*16 + coq*2 + gg)*2    ], s);
            atomicAdd(&g_fstats[(b*16 + coq*2 + gg)*2 + 1], ss);
        }
    }
}

// ---------------- final GN ----------------
__global__ void kFinalGN(const float* __restrict__ gng, const float* __restrict__ gnb,
                         float* __restrict__ out){
    int idx = blockIdx.x*256 + threadIdx.x;
    int b = idx >> 20;
    int c = (idx >> 14) & 63;
    int g = c >> 2;
    float s  = g_fstats[(b*16+g)*2];
    float ss = g_fstats[(b*16+g)*2+1];
    float mu = s * (1.f/65536.f);
    float var = ss * (1.f/65536.f) - mu*mu;
    float rs = rsqrtf(var + 1e-5f);
    out[idx] = (g_outraw[idx] - mu)*rs*gng[c] + gnb[c];
}

extern "C" void kernel_launch(void* const* d_in, const int* in_sizes, int n_in,
                              void* d_out, int out_size){
    const float* x     = (const float*)d_in[0];
    const float* offw  = (const float*)d_in[1];
    const float* offb  = (const float*)d_in[2];
    const float* gnog  = (const float*)d_in[3];
    const float* gnob  = (const float*)d_in[4];
    const float* altho = (const float*)d_in[5];
    const float* ipw   = (const float*)d_in[6];
    const float* cw    = (const float*)d_in[7];
    const float* cb    = (const float*)d_in[8];
    const float* xpw   = (const float*)d_in[9];
    const float* dtw   = (const float*)d_in[10];
    const float* dtb   = (const float*)d_in[11];
    const float* Alog  = (const float*)d_in[12];
    const float* Dp    = (const float*)d_in[13];
    const float* opw   = (const float*)d_in[14];
    const float* dscw  = (const float*)d_in[15];
    const float* dscb  = (const float*)d_in[16];
    const float* gng   = (const float*)d_in[17];
    const float* gnb   = (const float*)d_in[18];
    float* out = (float*)d_out;

    cudaFuncSetAttribute(kConv,   cudaFuncAttributeMaxDynamicSharedMemorySize, CONV_SMEM);
    cudaFuncSetAttribute(kScan1,  cudaFuncAttributeMaxDynamicSharedMemorySize, SCAN1_SMEM);
    cudaFuncSetAttribute(kScan3,  cudaFuncAttributeMaxDynamicSharedMemorySize, SCAN3_SMEM);
    cudaFuncSetAttribute(kDeform, cudaFuncAttributeMaxDynamicSharedMemorySize, DEF_SMEM);

    kZero<<<1, 128>>>();
    kTranspose<<<dim3(512, 2, 4), dim3(32, 8)>>>(x);
    kPrepW<<<144, 256>>>(dscw);
    kConv<<<dim3(128, 4), 128, CONV_SMEM>>>(offw, offb);
    kFinishOff<<<dim3(64, 4), 256>>>(gnog, gnob);
    kFrontEnd<<<dim3(64, 4), 256>>>(ipw, cw, cb, xpw, dtw, dtb);
    kScan1<<<dim3(64, 4), 288, SCAN1_SMEM>>>(Alog);
    kScan2<<<4, 288>>>();
    kScan3<<<dim3(64, 4), 288, SCAN3_SMEM>>>(Alog, Dp, opw, altho);
    kDeform<<<dim3(128, 4), 256, DEF_SMEM>>>(dscb);
    kFinalGN<<<16384, 256>>>(gng, gnb, out);
}

// round 3
// speedup vs baseline: 1.2158x; 1.2158x over previous
#include <cuda_runtime.h>
#include <math.h>

#define Bn   4
#define HWp  16384
#define LSEQ 16384

// ---------------- scratch ----------------
__device__ float g_xT[Bn*HWp*64];        // [b][pix][c]
__device__ float g_rawoff[Bn*10*HWp];    // offset conv out, [b][co][pix]
__device__ float g_ostats[Bn*5*2];
__device__ float g_seq[Bn*9*LSEQ];       // [b][m][l]
__device__ float g_ynew[Bn*9*HWp];       // [b][k][pix]
__device__ float g_dt[Bn*18*LSEQ];
__device__ float g_xi[Bn*18*LSEQ];
__device__ float g_gate[Bn*18*LSEQ];     // silu(z)
__device__ float g_Bsc[Bn*16*LSEQ];
__device__ float g_Csc[Bn*16*LSEQ];
__device__ float g_P[Bn*64*288];
__device__ float g_Q[Bn*64*288];
__device__ float g_hinit[Bn*64*288];
__device__ float g_py[Bn*9*HWp];         // [b][k][pix]
__device__ float g_wT[9*64*64];          // [k][ci][co]
__device__ float g_outraw[Bn*64*HWp];
__device__ float g_fstats[Bn*16*2];

__device__ __forceinline__ float softplusf(float x){
    return x > 20.f ? x : log1pf(expf(x));
}
__device__ __forceinline__ float siluf(float x){
    return x / (1.f + expf(-x));
}

// ---------------- zero stats ----------------
__global__ void kZero(){
    int t = threadIdx.x;
    if (t < 40)  g_ostats[t] = 0.f;
    if (t < 128) g_fstats[t] = 0.f;
}

// ---------------- transpose x ----------------
__global__ void kTranspose(const float* __restrict__ x){
    __shared__ float tile[32][33];
    int b = blockIdx.z, c0 = blockIdx.y*32, p0 = blockIdx.x*32;
    for (int i = threadIdx.y; i < 32; i += 8)
        tile[i][threadIdx.x] = x[(size_t)(b*64 + c0 + i)*HWp + p0 + threadIdx.x];
    __syncthreads();
    for (int i = threadIdx.y; i < 32; i += 8)
        g_xT[(size_t)(b*HWp + p0 + i)*64 + c0 + threadIdx.x] = tile[threadIdx.x][i];
}

// ---------------- weight transpose for deform conv ----------------
__global__ void kPrepW(const float* __restrict__ dscw){
    int idx = blockIdx.x*256 + threadIdx.x;
    if (idx >= 9*64*64) return;
    int k = idx >> 12; int r = idx & 4095;
    int ci = r >> 6;  int co = r & 63;
    g_wT[idx] = dscw[(co*64 + ci)*9 + k];
}

// ---------------- offset conv 3x3 64->10, register-tiled + GN stats ----------------
// thread = (co, wtile-of-8, row hh); warp = one co -> weight LDS = broadcast.
// c tiled in chunks of 16; smem: x tile [16c][4 rows][132] + all 5760 weights.
#define CONV_SMEM ((16*4*132 + 5760)*4)
__global__ void __launch_bounds__(320) kConv(const float* __restrict__ x,
                                             const float* __restrict__ offw,
                                             const float* __restrict__ offb){
    extern __shared__ float sm[];
    float* xs = sm;            // [c][r][ww], stride 132, ww = global w + 1
    float* sW = sm + 16*4*132; // offw[0..5759] direct copy: [co][c][dy][dx]
    int hb = blockIdx.x, b = blockIdx.y, tid = threadIdx.x;
    int h0 = hb*2;
    int hh = tid & 1, wt = (tid >> 1) & 15, co = tid >> 5;
    int w0 = wt*8;

    for (int idx = tid; idx < 5760; idx += 320) sW[idx] = offw[idx];

    float acc[8];
    float bv = offb[co];
    #pragma unroll
    for (int i = 0; i < 8; i++) acc[i] = bv;

    for (int cc = 0; cc < 4; cc++){
        int c0 = cc*16;
        __syncthreads();
        for (int idx = tid; idx < 16*4*130; idx += 320){
            int c = idx / 520;
            int rem = idx - c*520;
            int rr = rem / 130;
            int ww = rem - rr*130;
            int gh = h0 - 1 + rr, gw = ww - 1;
            float v = 0.f;
            if (gh >= 0 && gh < 128 && gw >= 0 && gw < 128)
                v = x[((size_t)(b*64 + c0 + c)*128 + gh)*128 + gw];
            xs[(c*4 + rr)*132 + ww] = v;
        }
        __syncthreads();
        for (int c = 0; c < 16; c++){
            #pragma unroll
            for (int dy = 0; dy < 3; dy++){
                const float* wp = &sW[(co*64 + c0 + c)*9 + dy*3];
                float wA = wp[0], wB = wp[1], wC = wp[2];
                const float* row = &xs[(c*4 + hh + dy)*132];
                float4 vA = *(const float4*)&row[w0];
                float4 vB = *(const float4*)&row[w0+4];
                float v8 = row[w0+8], v9 = row[w0+9];
                float v[10] = {vA.x,vA.y,vA.z,vA.w,vB.x,vB.y,vB.z,vB.w,v8,v9};
                #pragma unroll
                for (int i = 0; i < 8; i++)
                    acc[i] += wA*v[i] + wB*v[i+1] + wC*v[i+2];
            }
        }
    }

    int h = h0 + hh;
    float s = 0.f, ss = 0.f;
    #pragma unroll
    for (int i = 0; i < 8; i++){
        g_rawoff[((size_t)(b*10+co))*HWp + h*128 + w0 + i] = acc[i];
        s += acc[i]; ss += acc[i]*acc[i];
    }
    #pragma unroll
    for (int m = 16; m > 0; m >>= 1){
        s  += __shfl_xor_sync(0xffffffffu, s,  m);
        ss += __shfl_xor_sync(0xffffffffu, ss, m);
    }
    if ((tid & 31) == 0){
        atomicAdd(&g_ostats[(b*5 + (co>>1))*2    ], s);
        atomicAdd(&g_ostats[(b*5 + (co>>1))*2 + 1], ss);
    }
}

// ---------------- GN finalize + tanh + cumsum + seq + y_new ----------------
__global__ void kFinishOff(const float* __restrict__ gnog, const float* __restrict__ gnob){
    __shared__ float sMu[5], sRs[5];
    int b = blockIdx.y, tid = threadIdx.x;
    int p = blockIdx.x*256 + tid;
    if (tid < 5){
        float s  = g_ostats[(b*5+tid)*2];
        float ss = g_ostats[(b*5+tid)*2+1];
        float mu = s * (1.f/32768.f);
        float var = ss * (1.f/32768.f) - mu*mu;
        sMu[tid] = mu;
        sRs[tid] = rsqrtf(var + 1e-5f);
    }
    __syncthreads();

    float tv[9];
    #pragma unroll
    for (int c = 0; c < 9; c++){
        float raw = g_rawoff[((size_t)(b*10+c))*HWp + p];
        float xn = (raw - sMu[c>>1]) * sRs[c>>1] * gnog[c] + gnob[c];
        tv[c] = tanhf(xn);
    }
    float cum[9];
    cum[4] = 0.f;
    cum[5] = tv[5]; cum[6] = cum[5]+tv[6]; cum[7] = cum[6]+tv[7]; cum[8] = cum[7]+tv[8];
    cum[3] = tv[3]; cum[2] = cum[3]+tv[2]; cum[1] = cum[2]+tv[1]; cum[0] = cum[1]+tv[0];

    int h = p >> 7, w = p & 127;
    #pragma unroll
    for (int k = 0; k < 9; k++)
        g_ynew[((size_t)(b*9+k))*HWp + p] = (float)h + cum[k];

    int l = ((h>>1)*128 + w)*2 + (h&1);
    #pragma unroll
    for (int m = 0; m < 9; m++)
        g_seq[((size_t)(b*9+m))*LSEQ + l] = tv[m];
}

// ---------------- mamba front-end ----------------
__global__ void kFrontEnd(const float* __restrict__ ipw, const float* __restrict__ cw,
                          const float* __restrict__ cb,  const float* __restrict__ xpw,
                          const float* __restrict__ dtw, const float* __restrict__ dtb){
    __shared__ float sXP[259*19];
    __shared__ float sIPW[324], sXPW[594], sCW[72], sCB[18], sDTW[18], sDTB[18];
    int b = blockIdx.y, l0 = blockIdx.x*256, tid = threadIdx.x;
    int l = l0 + tid;

    for (int idx = tid; idx < 324; idx += 256) sIPW[idx] = ipw[idx];
    for (int idx = tid; idx < 594; idx += 256) sXPW[idx] = xpw[idx];
    if (tid < 72) sCW[tid] = cw[tid];
    if (tid < 18){ sCB[tid] = cb[tid]; sDTW[tid] = dtw[tid]; sDTB[tid] = dtb[tid]; }
    __syncthreads();

    float sq[9];
    #pragma unroll
    for (int m = 0; m < 9; m++) sq[m] = g_seq[((size_t)(b*9+m))*LSEQ + l];
    #pragma unroll
    for (int n = 0; n < 18; n++){
        float v = 0.f;
        #pragma unroll
        for (int m = 0; m < 9; m++) v += sq[m]*sIPW[n*9+m];
        sXP[(tid+3)*19 + n] = v;
    }
    #pragma unroll
    for (int n = 0; n < 18; n++){
        float z = 0.f;
        #pragma unroll
        for (int m = 0; m < 9; m++) z += sq[m]*sIPW[(18+n)*9+m];
        g_gate[((size_t)(b*18+n))*LSEQ + l] = siluf(z);
    }
    if (tid < 3){
        int l2 = l0 - 3 + tid;
        if (l2 >= 0){
            float s2[9];
            #pragma unroll
            for (int m = 0; m < 9; m++) s2[m] = g_seq[((size_t)(b*9+m))*LSEQ + l2];
            #pragma unroll
            for (int n = 0; n < 18; n++){
                float v = 0.f;
                #pragma unroll
                for (int m = 0; m < 9; m++) v += s2[m]*sIPW[n*9+m];
                sXP[tid*19 + n] = v;
            }
        } else {
            #pragma unroll
            for (int n = 0; n < 18; n++) sXP[tid*19 + n] = 0.f;
        }
    }
    __syncthreads();

    float xi[18];
    #pragma unroll
    for (int d = 0; d < 18; d++){
        float xc = sCB[d];
        #pragma unroll
        for (int j = 0; j < 4; j++) xc += sCW[d*4+j]*sXP[(tid+j)*19 + d];
        xi[d] = siluf(xc);
    }
    float dtr = 0.f;
    #pragma unroll
    for (int d = 0; d < 18; d++) dtr += xi[d]*sXPW[d];
    #pragma unroll
    for (int s = 0; s < 16; s++){
        float bv = 0.f, cv = 0.f;
        #pragma unroll
        for (int d = 0; d < 18; d++){
            bv += xi[d]*sXPW[(1+s)*18 + d];
            cv += xi[d]*sXPW[(17+s)*18 + d];
        }
        g_Bsc[((size_t)(b*16+s))*LSEQ + l] = bv;
        g_Csc[((size_t)(b*16+s))*LSEQ + l] = cv;
    }
    #pragma unroll
    for (int d = 0; d < 18; d++){
        float a = dtr*sDTW[d] + sDTB[d];
        g_dt[((size_t)(b*18+d))*LSEQ + l] = softplusf(a);
        g_xi[((size_t)(b*18+d))*LSEQ + l] = xi[d];
    }
}

// ---------------- scan pass1: per-chunk (P,Q) ----------------
#define SCAN1_SMEM (52*257*4)
__global__ void kScan1(const float* __restrict__ Alog){
    extern __shared__ float sm[];
    float* sDT = sm;
    float* sXI = sm + 18*257;
    float* sB  = sm + 36*257;
    int b = blockIdx.y, c = blockIdx.x, l0 = c*256, t = threadIdx.x;
    for (int idx = t; idx < 18*256; idx += 288){
        int dd = idx >> 8, i = idx & 255;
        sDT[dd*257+i] = g_dt[((size_t)(b*18+dd))*LSEQ + l0 + i];
        sXI[dd*257+i] = g_xi[((size_t)(b*18+dd))*LSEQ + l0 + i];
    }
    for (int idx = t; idx < 16*256; idx += 288){
        int ss = idx >> 8, i = idx & 255;
        sB[ss*257+i] = g_Bsc[((size_t)(b*16+ss))*LSEQ + l0 + i];
    }
    __syncthreads();
    int d = t / 16, s = t % 16;
    float a = -expf(Alog[d*16+s]);
    float p = 1.f, q = 0.f;
    for (int i = 0; i < 256; i++){
        float dt = sDT[d*257+i];
        float da = expf(dt*a);
        q = da*q + dt*sB[s*257+i]*sXI[d*257+i];
        p *= da;
    }
    g_P[(b*64+c)*288 + t] = p;
    g_Q[(b*64+c)*288 + t] = q;
}

// ---------------- scan pass2: serial carry ----------------
__global__ void kScan2(){
    int b = blockIdx.x, t = threadIdx.x;
    float h = 0.f;
    for (int c = 0; c < 64; c++){
        g_hinit[(b*64+c)*288 + t] = h;
        h = g_P[(b*64+c)*288 + t]*h + g_Q[(b*64+c)*288 + t];
    }
}

// ---------------- scan pass3: replay + output + py ----------------
#define SCAN3_SMEM ((86*257 + 162 + 18)*4)
__global__ void kScan3(const float* __restrict__ Alog, const float* __restrict__ Dp,
                       const float* __restrict__ opw,  const float* __restrict__ altho){
    extern __shared__ float sm[];
    float* sDT = sm;
    float* sXI = sm + 18*257;
    float* sB  = sm + 36*257;
    float* sC  = sm + 52*257;
    float* sYS = sm + 68*257;
    float* sOPW = sm + 86*257;
    float* sDP  = sOPW + 162;
    int b = blockIdx.y, c = blockIdx.x, l0 = c*256, t = threadIdx.x;
    for (int idx = t; idx < 18*256; idx += 288){
        int dd = idx >> 8, i = idx & 255;
        sDT[dd*257+i] = g_dt[((size_t)(b*18+dd))*LSEQ + l0 + i];
        sXI[dd*257+i] = g_xi[((size_t)(b*18+dd))*LSEQ + l0 + i];
    }
    for (int idx = t; idx < 16*256; idx += 288){
        int ss = idx >> 8, i = idx & 255;
        sB[ss*257+i] = g_Bsc[((size_t)(b*16+ss))*LSEQ + l0 + i];
        sC[ss*257+i] = g_Csc[((size_t)(b*16+ss))*LSEQ + l0 + i];
    }
    if (t < 162) sOPW[t] = opw[t];
    if (t < 18)  sDP[t]  = Dp[t];
    __syncthreads();

    int d = t / 16, s = t % 16;
    float a = -expf(Alog[d*16+s]);
    float h = g_hinit[(b*64+c)*288 + t];
    for (int i = 0; i < 256; i++){
        float dt = sDT[d*257+i];
        float da = expf(dt*a);
        h = da*h + dt*sB[s*257+i]*sXI[d*257+i];
        float v = h * sC[s*257+i];
        v += __shfl_xor_sync(0xffffffffu, v, 1);
        v += __shfl_xor_sync(0xffffffffu, v, 2);
        v += __shfl_xor_sync(0xffffffffu, v, 4);
        v += __shfl_xor_sync(0xffffffffu, v, 8);
        if ((t & 15) == 0) sYS[d*257+i] = v;
    }
    __syncthreads();

    if (t < 256){
        int l = l0 + t;
        float wgt = fmaxf(softplusf(altho[0]), 0.01f);
        float ym[9];
        #pragma unroll
        for (int m = 0; m < 9; m++) ym[m] = 0.f;
        #pragma unroll
        for (int dd = 0; dd < 18; dd++){
            float yv = (sYS[dd*257+t] + sDP[dd]*sXI[dd*257+t]) * g_gate[((size_t)(b*18+dd))*LSEQ + l];
            #pragma unroll
            for (int m = 0; m < 9; m++) ym[m] += yv * sOPW[m*18+dd];
        }
        int tt = l & 1, r = l >> 1;
        int w = r & 127, h2 = r >> 7;
        int pix = (h2*2 + tt)*128 + w;
        #pragma unroll
        for (int m = 0; m < 9; m++){
            float py = wgt*ym[m] + g_ynew[((size_t)(b*9+m))*HWp + pix];
            py = fminf(fmaxf(py, 0.f), 127.f);
            g_py[((size_t)(b*9+m))*HWp + pix] = py;
        }
    }
}

// ---------------- deformable gather + 64x576 contraction + GN stats ----------------
#define DEF_SMEM (12288*4)
__global__ void __launch_bounds__(256) kDeform(const float* __restrict__ dscb){
    extern __shared__ float sm[];
    float* sVal = sm;          // [ci][j] 64x128
    float* sW   = sm + 8192;   // [ci][co] 64x64
    int i = blockIdx.x, b = blockIdx.y, t = threadIdx.x;
    int coq = t >> 5, lq = t & 31;
    int j = t >> 1, half = t & 1;

    float acc[4][8];
    #pragma unroll
    for (int a = 0; a < 4; a++)
        #pragma unroll
        for (int c2 = 0; c2 < 8; c2++) acc[a][c2] = 0.f;

    for (int k = 0; k < 9; k++){
        #pragma unroll
        for (int r = 0; r < 16; r++) sW[t + 256*r] = g_wT[k*4096 + t + 256*r];

        float pyv = g_py[((size_t)(b*9+k))*HWp + i*128 + j];
        int y0 = (int)floorf(pyv);
        float wy = pyv - (float)y0;
        int y1 = min(y0 + 1, 127);
        int xc = min(max(j + k - 4, 0), 127);
        const float* r0 = &g_xT[((size_t)b*HWp + y0*128 + xc)*64 + half*32];
        const float* r1 = &g_xT[((size_t)b*HWp + y1*128 + xc)*64 + half*32];
        float wy0 = 1.f - wy;
        #pragma unroll
        for (int c2 = 0; c2 < 32; c2++)
            sVal[(half*32 + c2)*128 + j] = r0[c2]*wy0 + r1[c2]*wy;
        __syncthreads();

        #pragma unroll 2
        for (int ci = 0; ci < 64; ci++){
            float v0 = sVal[ci*128 + lq];
            float v1 = sVal[ci*128 + lq + 32];
            float v2 = sVal[ci*128 + lq + 64];
            float v3 = sVal[ci*128 + lq + 96];
            float4 wA = *(const float4*)&sW[ci*64 + coq*8];
            float4 wB = *(const float4*)&sW[ci*64 + coq*8 + 4];
            float wv[8] = {wA.x, wA.y, wA.z, wA.w, wB.x, wB.y, wB.z, wB.w};
            float vv[4] = {v0, v1, v2, v3};
            #pragma unroll
            for (int jj = 0; jj < 4; jj++)
                #pragma unroll
                for (int c2 = 0; c2 < 8; c2++)
                    acc[jj][c2] += wv[c2]*vv[jj];
        }
        __syncthreads();
    }

    float gs[2] = {0.f, 0.f}, gss[2] = {0.f, 0.f};
    #pragma unroll
    for (int c2 = 0; c2 < 8; c2++){
        int co = coq*8 + c2;
        float bsv = dscb[co];
        #pragma unroll
        for (int jj = 0; jj < 4; jj++){
            float v = acc[jj][c2] + bsv;
            g_outraw[((size_t)(b*64+co))*HWp + i*128 + lq + 32*jj] = v;
            gs[c2>>2] += v; gss[c2>>2] += v*v;
        }
    }
    #pragma unroll
    for (int gg = 0; gg < 2; gg++){
        float s = gs[gg], ss = gss[gg];
        #pragma unroll
        for (int m = 16; m > 0; m >>= 1){
            s  += __shfl_xor_sync(0xffffffffu, s,  m);
            ss += __shfl_xor_sync(0xffffffffu, ss, m);
        }
        if (lq == 0){
            atomicAdd(&g_fstats[(b*16 + coq*2 + gg)*2    ], s);
            atomicAdd(&g_fstats[(b*16 + coq*2 + gg)*2 + 1], ss);
        }
    }
}

// ---------------- final GN ----------------
__global__ void kFinalGN(const float* __restrict__ gng, const float* __restrict__ gnb,
                         float* __restrict__ out){
    int idx = blockIdx.x*256 + threadIdx.x;
    int b = idx >> 20;
    int c = (idx >> 14) & 63;
    int g = c >> 2;
    float s  = g_fstats[(b*16+g)*2];
    float ss = g_fstats[(b*16+g)*2+1];
    float mu = s * (1.f/65536.f);
    float var = ss * (1.f/65536.f) - mu*mu;
    float rs = rsqrtf(var + 1e-5f);
    out[idx] = (g_outraw[idx] - mu)*rs*gng[c] + gnb[c];
}

extern "C" void kernel_launch(void* const* d_in, const int* in_sizes, int n_in,
                              void* d_out, int out_size){
    const float* x     = (const float*)d_in[0];
    const float* offw  = (const float*)d_in[1];
    const float* offb  = (const float*)d_in[2];
    const float* gnog  = (const float*)d_in[3];
    const float* gnob  = (const float*)d_in[4];
    const float* altho = (const float*)d_in[5];
    const float* ipw   = (const float*)d_in[6];
    const float* cw    = (const float*)d_in[7];
    const float* cb    = (const float*)d_in[8];
    const float* xpw   = (const float*)d_in[9];
    const float* dtw   = (const float*)d_in[10];
    const float* dtb   = (const float*)d_in[11];
    const float* Alog  = (const float*)d_in[12];
    const float* Dp    = (const float*)d_in[13];
    const float* opw   = (const float*)d_in[14];
    const float* dscw  = (const float*)d_in[15];
    const float* dscb  = (const float*)d_in[16];
    const float* gng   = (const float*)d_in[17];
    const float* gnb   = (const float*)d_in[18];
    float* out = (float*)d_out;

    cudaFuncSetAttribute(kConv,   cudaFuncAttributeMaxDynamicSharedMemorySize, CONV_SMEM);
    cudaFuncSetAttribute(kScan1,  cudaFuncAttributeMaxDynamicSharedMemorySize, SCAN1_SMEM);
    cudaFuncSetAttribute(kScan3,  cudaFuncAttributeMaxDynamicSharedMemorySize, SCAN3_SMEM);
    cudaFuncSetAttribute(kDeform, cudaFuncAttributeMaxDynamicSharedMemorySize, DEF_SMEM);

    kZero<<<1, 128>>>();
    kTranspose<<<dim3(512, 2, 4), dim3(32, 8)>>>(x);
    kPrepW<<<144, 256>>>(dscw);
    kConv<<<dim3(64, 4), 320, CONV_SMEM>>>(x, offw, offb);
    kFinishOff<<<dim3(64, 4), 256>>>(gnog, gnob);
    kFrontEnd<<<dim3(64, 4), 256>>>(ipw, cw, cb, xpw, dtw, dtb);
    kScan1<<<dim3(64, 4), 288, SCAN1_SMEM>>>(Alog);
    kScan2<<<4, 288>>>();
    kScan3<<<dim3(64, 4), 288, SCAN3_SMEM>>>(Alog, Dp, opw, altho);
    kDeform<<<dim3(128, 4), 256, DEF_SMEM>>>(dscb);
    kFinalGN<<<16384, 256>>>(gng, gnb, out);
}